// round 12
// baseline (speedup 1.0000x reference)
#include <cuda_runtime.h>
#include <cuda_bf16.h>
#include <math.h>

#define TT 2048
#define DM 1024
#define NH 16
#define HDI 64
#define BB 2
#define MT (BB*TT)     // 4096
#define GS 40          // proj smem stride (bf16): 80B/row -> conflict-free ldmatrix

// proj pipeline: 4 stages, each A(10240B)+B(10240B)
#define PSTG 20480
#define PSMEM (4*PSTG)
// attn pipeline: 3 stages, each K(18432B)+V(18432B); Q staged via stage2 K region
#define ASTG 36864
#define ASMEM (3*ASTG)

typedef __nv_bfloat16 bf16;
typedef __nv_bfloat162 bf162;

// ---------------- scratch (__device__ globals; no allocation) ----------------
__device__ bf16 g_Xb[MT*DM];              // x in bf16
__device__ bf16 g_Wb[4][DM*DM];           // weights bf16 (q,k,v,o)
__device__ bf16 g_Qb[BB*NH*TT*HDI];       // per-head [B,H,T,64]
__device__ bf16 g_Kb[BB*NH*TT*HDI];
__device__ bf16 g_Vb[BB*NH*TT*HDI];
__device__ bf16 g_Ob[MT*DM];              // attn out [B,T,D] bf16 (A of out-proj)

// ---------------- helpers ----------------
__device__ __forceinline__ unsigned pack2(float a, float b) {
    bf162 t = __floats2bfloat162_rn(a, b);
    return *reinterpret_cast<unsigned*>(&t);
}
__device__ __forceinline__ void st2(bf16* p, bf16 a, bf16 b) {
    bf162 t; t.x = a; t.y = b;
    *reinterpret_cast<bf162*>(p) = t;
}
__device__ __forceinline__ void mma16816(float* c,
    unsigned a0, unsigned a1, unsigned a2, unsigned a3, unsigned b0, unsigned b1) {
    asm volatile(
        "mma.sync.aligned.m16n8k16.row.col.f32.bf16.bf16.f32 "
        "{%0,%1,%2,%3},{%4,%5,%6,%7},{%8,%9},{%0,%1,%2,%3};\n"
        : "+f"(c[0]), "+f"(c[1]), "+f"(c[2]), "+f"(c[3])
        : "r"(a0), "r"(a1), "r"(a2), "r"(a3), "r"(b0), "r"(b1));
}
__device__ __forceinline__ void ldsm4(unsigned& r0, unsigned& r1, unsigned& r2, unsigned& r3, unsigned addr) {
    asm volatile("ldmatrix.sync.aligned.m8n8.x4.shared.b16 {%0,%1,%2,%3},[%4];\n"
        : "=r"(r0), "=r"(r1), "=r"(r2), "=r"(r3) : "r"(addr));
}
__device__ __forceinline__ void ldsm4t(unsigned& r0, unsigned& r1, unsigned& r2, unsigned& r3, unsigned addr) {
    asm volatile("ldmatrix.sync.aligned.m8n8.x4.trans.shared.b16 {%0,%1,%2,%3},[%4];\n"
        : "=r"(r0), "=r"(r1), "=r"(r2), "=r"(r3) : "r"(addr));
}
__device__ __forceinline__ void cpa16(unsigned dst, const void* src) {
    asm volatile("cp.async.cg.shared.global [%0], [%1], 16;" :: "r"(dst), "l"(src));
}
#define CP_COMMIT() asm volatile("cp.async.commit_group;")
#define CP_WAIT2()  asm volatile("cp.async.wait_group 2;")
#define CP_WAIT1()  asm volatile("cp.async.wait_group 1;")
#define CP_WAIT0()  asm volatile("cp.async.wait_group 0;")

// sigmoid(s/8) = 0.5*tanh(s/16)+0.5  (single MUFU via tanh.approx)
__device__ __forceinline__ float sigm8(float s) {
    float t;
    asm("tanh.approx.f32 %0, %1;" : "=f"(t) : "f"(s * 0.0625f));
    return fmaf(t, 0.5f, 0.5f);
}

// ---------------- fp32 -> bf16, all 5 tensors in one launch ----------------
__global__ void cvt_all(const float* __restrict__ x,
                        const float* __restrict__ wq, const float* __restrict__ wk,
                        const float* __restrict__ wv, const float* __restrict__ wo)
{
    int b = blockIdx.x;
    const float* src;
    bf16* dst;
    if (b < 4096) {
        src = x + (size_t)b * 1024;
        dst = g_Xb + (size_t)b * 1024;
    } else {
        int w = (b - 4096) >> 10, r = (b - 4096) & 1023;
        src = ((w == 0) ? wq : (w == 1) ? wk : (w == 2) ? wv : wo) + (size_t)r * 1024;
        dst = g_Wb[w] + (size_t)r * 1024;
    }
    size_t i = (size_t)threadIdx.x * 4;
    float4 v = *(const float4*)(src + i);
    *(bf162*)(dst + i)     = __floats2bfloat162_rn(v.x, v.y);
    *(bf162*)(dst + i + 2) = __floats2bfloat162_rn(v.z, v.w);
}

// ---------------- projection GEMM: 4 warps, warp tile 64x64 ----------------
// C[M=4096,N=1024] = A[M,1024] . W[N,1024]^T (+bias)
// grid.z + base_mode -> mode. 0/1/2: per-head Q/K/V; 3: out = x + alpha*(C+bias)
__global__ __launch_bounds__(128, 2) void proj_mma(
    const float* __restrict__ b0p, const float* __restrict__ b1p,
    const float* __restrict__ b2p, int base_mode,
    const float* __restrict__ xres, const float* __restrict__ alphap,
    float* __restrict__ outf)
{
    extern __shared__ char smraw[];
    const int tid  = threadIdx.x;
    const int lane = tid & 31, wid = tid >> 5;
    const int wm = wid >> 1, wn = wid & 1;       // 2x2 warps; warp tile 64x64
    const int mode = base_mode + blockIdx.z;
    const float* bias = (blockIdx.z == 0) ? b0p : (blockIdx.z == 1) ? b1p : b2p;
    const int bm = blockIdx.y * 128, bn = blockIdx.x * 128;

    const bf16* A = (mode == 3) ? g_Ob : g_Xb;
    const bf16* W = g_Wb[mode];
    const bf16* Ag = A + (size_t)bm * DM;
    const bf16* Wg = W + (size_t)bn * DM;

    unsigned sb = (unsigned)__cvta_generic_to_shared(smraw);

    // issue k-chunk kt into stage s (512 16B chunks per matrix; 4+4 per thread)
    auto issue = [&](int kt, int s) {
        const unsigned dA = sb + (unsigned)s * PSTG;
        const unsigned dB = dA + 10240;
        const int koff = kt * 32;
        #pragma unroll
        for (int i = 0; i < 4; i++) {
            int e = tid + i * 128;
            int row = e >> 2, c16 = e & 3;
            cpa16(dA + row * 80 + c16 * 16, Ag + (size_t)row * DM + koff + c16 * 8);
            cpa16(dB + row * 80 + c16 * 16, Wg + (size_t)row * DM + koff + c16 * 8);
        }
        CP_COMMIT();
    };

    float c[4][8][4];
    #pragma unroll
    for (int i = 0; i < 4; i++)
        #pragma unroll
        for (int j = 0; j < 8; j++)
            #pragma unroll
            for (int q = 0; q < 4; q++) c[i][j][q] = 0.f;

    const int a_row  = lane & 15;
    const int a_coff = (lane >> 4) << 3;
    const int b_row  = (lane & 7) + ((lane >> 4) << 3);
    const int b_coff = lane & 8;

    issue(0, 0);
    issue(1, 1);
    issue(2, 2);

    for (int kt = 0; kt < 32; kt++) {
        if (kt < 30) CP_WAIT2();
        else if (kt == 30) CP_WAIT1();
        else CP_WAIT0();
        __syncthreads();
        if (kt + 3 < 32) issue(kt + 3, (kt + 3) & 3);

        const unsigned cA = sb + (unsigned)(kt & 3) * PSTG;
        const unsigned cB = cA + 10240;
        #pragma unroll
        for (int d = 0; d < 32; d += 16) {
            unsigned af[4][4];
            #pragma unroll
            for (int mi = 0; mi < 4; mi++)
                ldsm4(af[mi][0], af[mi][1], af[mi][2], af[mi][3],
                      cA + (unsigned)(((wm * 64 + mi * 16 + a_row) * GS + d + a_coff) * 2));
            #pragma unroll
            for (int np = 0; np < 4; np++) {
                unsigned b0, b1, b2, b3;
                ldsm4(b0, b1, b2, b3,
                      cB + (unsigned)(((wn * 64 + np * 16 + b_row) * GS + d + b_coff) * 2));
                #pragma unroll
                for (int mi = 0; mi < 4; mi++) {
                    mma16816(c[mi][np * 2],     af[mi][0], af[mi][1], af[mi][2], af[mi][3], b0, b1);
                    mma16816(c[mi][np * 2 + 1], af[mi][0], af[mi][1], af[mi][2], af[mi][3], b2, b3);
                }
            }
        }
    }

    // epilogue
    const int g  = lane >> 2;
    const int q2 = (lane & 3) * 2;
    if (mode == 3) {
        const float alpha = *alphap;
        #pragma unroll
        for (int mi = 0; mi < 4; mi++)
            #pragma unroll
            for (int half = 0; half < 2; half++) {
                int m = bm + wm * 64 + mi * 16 + g + half * 8;
                #pragma unroll
                for (int ni = 0; ni < 8; ni++) {
                    int n = bn + wn * 64 + ni * 8 + q2;
                    float2 o;
                    o.x = xres[(size_t)m * DM + n]     + alpha * (c[mi][ni][half * 2 + 0] + bias[n]);
                    o.y = xres[(size_t)m * DM + n + 1] + alpha * (c[mi][ni][half * 2 + 1] + bias[n + 1]);
                    *(float2*)&outf[(size_t)m * DM + n] = o;
                }
            }
    } else {
        bf16* outp = (mode == 0) ? g_Qb : (mode == 1) ? g_Kb : g_Vb;
        #pragma unroll
        for (int mi = 0; mi < 4; mi++)
            #pragma unroll
            for (int half = 0; half < 2; half++) {
                int m = bm + wm * 64 + mi * 16 + g + half * 8;
                int b_ = m >> 11, t_ = m & 2047;
                #pragma unroll
                for (int ni = 0; ni < 8; ni++) {
                    int n = bn + wn * 64 + ni * 8 + q2;
                    int h = n >> 6, hd = n & 63;
                    size_t rb = ((size_t)(b_ * NH + h) * TT + t_);
                    float v0 = c[mi][ni][half * 2 + 0] + bias[n];
                    float v1 = c[mi][ni][half * 2 + 1] + bias[n + 1];
                    st2(&outp[rb * 64 + hd],
                        __float2bfloat16_rn(v0), __float2bfloat16_rn(v1));
                }
            }
    }
}

// ---------------- attention: 4 warps, warp = 32 q-rows x 128 keys ----------------
// CTA = (b*H+h, 128-q tile); Q in regs, cp.async 3-stage K/V, 1 barrier/iter.
__global__ __launch_bounds__(128, 2) void attn_mma()
{
    extern __shared__ char smraw[];
    const int tid = threadIdx.x, lane = tid & 31, wid = tid >> 5;
    const int bh = blockIdx.x, qt = blockIdx.y;
    const bf16* Qg = g_Qb + (size_t)(bh * TT + qt * 128) * 64;
    const bf16* Kg = g_Kb + (size_t)bh * TT * 64;
    const bf16* Vg = g_Vb + (size_t)bh * TT * 64;

    unsigned sb = (unsigned)__cvta_generic_to_shared(smraw);

    // issue K/V tile t into stage s (1024 chunks each matrix; 8+8 per thread)
    auto issueKV = [&](int t, int s) {
        const bf16* Kt = Kg + (size_t)t * 128 * 64;
        const bf16* Vt = Vg + (size_t)t * 128 * 64;
        const unsigned dK = sb + (unsigned)s * ASTG;
        const unsigned dV = dK + 18432;
        #pragma unroll
        for (int i = 0; i < 8; i++) {
            int e = tid + i * 128;
            int row = e >> 3, c16 = e & 7;
            cpa16(dK + row * 144 + c16 * 16, Kt + (size_t)row * 64 + c16 * 8);
            cpa16(dV + row * 144 + c16 * 16, Vt + (size_t)row * 64 + c16 * 8);
        }
        CP_COMMIT();
    };

    // prologue: tiles 0,1 into stages 0,1; Q into stage2's K region
    issueKV(0, 0);
    issueKV(1, 1);
    {
        const unsigned dQ = sb + 2u * ASTG;
        #pragma unroll
        for (int i = 0; i < 8; i++) {
            int e = tid + i * 128;
            int row = e >> 3, c16 = e & 7;
            cpa16(dQ + row * 144 + c16 * 16, Qg + (size_t)row * 64 + c16 * 8);
        }
        CP_COMMIT();
    }

    const int a_row  = lane & 15;
    const int a_coff = (lane >> 4) << 3;
    const int b_row  = (lane & 7) + ((lane >> 4) << 3);
    const int b_coff = lane & 8;
    const int v_row  = (lane & 7) + (lane & 8);
    const int v_coff = (lane >> 4) << 3;
    const int qr = wid * 32;                      // 32 q-rows per warp

    CP_WAIT0();
    __syncthreads();

    // hoist Q fragments for both 16-row m-tiles
    unsigned qf[2][4][4];
    #pragma unroll
    for (int mt = 0; mt < 2; mt++)
        #pragma unroll
        for (int d16 = 0; d16 < 4; d16++)
            ldsm4(qf[mt][d16][0], qf[mt][d16][1], qf[mt][d16][2], qf[mt][d16][3],
                  sb + 2u * ASTG + (unsigned)(((qr + mt * 16 + a_row) * 144) + (d16 * 16 + a_coff) * 2));

    float oc[2][8][4];
    #pragma unroll
    for (int mt = 0; mt < 2; mt++)
        #pragma unroll
        for (int i = 0; i < 8; i++)
            #pragma unroll
            for (int j = 0; j < 4; j++) oc[mt][i][j] = 0.f;
    float ds[2][2] = {{0.f, 0.f}, {0.f, 0.f}};

    for (int kt = 0; kt < 16; kt++) {
        if (kt == 15) CP_WAIT0(); else CP_WAIT1();
        __syncthreads();
        if (kt + 2 < 16) issueKV(kt + 2, (kt + 2) % 3);

        const unsigned cK = sb + (unsigned)(kt % 3) * ASTG;
        const unsigned cV = cK + 18432;

        #pragma unroll
        for (int half = 0; half < 2; half++) {
            float sc[2][8][4];
            #pragma unroll
            for (int mt = 0; mt < 2; mt++)
                #pragma unroll
                for (int i = 0; i < 8; i++)
                    #pragma unroll
                    for (int j = 0; j < 4; j++) sc[mt][i][j] = 0.f;

            #pragma unroll
            for (int np = 0; np < 4; np++) {
                const int npg = half * 4 + np;
                #pragma unroll
                for (int d16 = 0; d16 < 4; d16++) {
                    unsigned b0, b1, b2, b3;
                    ldsm4(b0, b1, b2, b3,
                          cK + (unsigned)(((npg * 16 + b_row) * 144) + (d16 * 16 + b_coff) * 2));
                    #pragma unroll
                    for (int mt = 0; mt < 2; mt++) {
                        mma16816(sc[mt][np * 2],     qf[mt][d16][0], qf[mt][d16][1],
                                 qf[mt][d16][2], qf[mt][d16][3], b0, b1);
                        mma16816(sc[mt][np * 2 + 1], qf[mt][d16][0], qf[mt][d16][1],
                                 qf[mt][d16][2], qf[mt][d16][3], b2, b3);
                    }
                }
            }

            #pragma unroll
            for (int mt = 0; mt < 2; mt++)
                #pragma unroll
                for (int nt = 0; nt < 8; nt++) {
                    float g0 = sigm8(sc[mt][nt][0]);
                    float g1 = sigm8(sc[mt][nt][1]);
                    float g2 = sigm8(sc[mt][nt][2]);
                    float g3 = sigm8(sc[mt][nt][3]);
                    sc[mt][nt][0] = g0; sc[mt][nt][1] = g1;
                    sc[mt][nt][2] = g2; sc[mt][nt][3] = g3;
                    ds[mt][0] += g0 + g1;
                    ds[mt][1] += g2 + g3;
                }

            #pragma unroll
            for (int t = 0; t < 4; t++) {
                const int tg = half * 4 + t;
                unsigned a[2][4];
                #pragma unroll
                for (int mt = 0; mt < 2; mt++) {
                    a[mt][0] = pack2(sc[mt][2 * t][0],     sc[mt][2 * t][1]);
                    a[mt][1] = pack2(sc[mt][2 * t][2],     sc[mt][2 * t][3]);
                    a[mt][2] = pack2(sc[mt][2 * t + 1][0], sc[mt][2 * t + 1][1]);
                    a[mt][3] = pack2(sc[mt][2 * t + 1][2], sc[mt][2 * t + 1][3]);
                }
                #pragma unroll
                for (int nq = 0; nq < 4; nq++) {
                    unsigned b0, b1, b2, b3;
                    ldsm4t(b0, b1, b2, b3,
                           cV + (unsigned)(((tg * 16 + v_row) * 144) + (nq * 16 + v_coff) * 2));
                    #pragma unroll
                    for (int mt = 0; mt < 2; mt++) {
                        mma16816(oc[mt][nq * 2],     a[mt][0], a[mt][1], a[mt][2], a[mt][3], b0, b1);
                        mma16816(oc[mt][nq * 2 + 1], a[mt][0], a[mt][1], a[mt][2], a[mt][3], b2, b3);
                    }
                }
            }
        }
    }

    // denominator reduce across the quad
    #pragma unroll
    for (int mt = 0; mt < 2; mt++)
        #pragma unroll
        for (int hh = 0; hh < 2; hh++) {
            ds[mt][hh] += __shfl_xor_sync(0xffffffffu, ds[mt][hh], 1);
            ds[mt][hh] += __shfl_xor_sync(0xffffffffu, ds[mt][hh], 2);
        }

    // epilogue: normalized O -> g_Ob [B,T,D] bf16
    const int b_ = bh >> 4, h = bh & 15;
    const int g = lane >> 2, q2 = (lane & 3) * 2;
    #pragma unroll
    for (int mt = 0; mt < 2; mt++) {
        const float inv0 = 1.f / (ds[mt][0] + 1e-6f);
        const float inv1 = 1.f / (ds[mt][1] + 1e-6f);
        const int t0 = qt * 128 + qr + mt * 16 + g;
        const size_t r0 = (size_t)(b_ * TT + t0) * DM + h * 64;
        const size_t r1 = r0 + (size_t)8 * DM;
        #pragma unroll
        for (int nt = 0; nt < 8; nt++) {
            int hd = nt * 8 + q2;
            st2(&g_Ob[r0 + hd], __float2bfloat16_rn(oc[mt][nt][0] * inv0),
                                __float2bfloat16_rn(oc[mt][nt][1] * inv0));
            st2(&g_Ob[r1 + hd], __float2bfloat16_rn(oc[mt][nt][2] * inv1),
                                __float2bfloat16_rn(oc[mt][nt][3] * inv1));
        }
    }
}

// ---------------------------------------------------------------------------
extern "C" void kernel_launch(void* const* d_in, const int* in_sizes, int n_in,
                              void* d_out, int out_size)
{
    const float* x  = (const float*)d_in[0];
    const float* wq = (const float*)d_in[1];
    const float* bq = (const float*)d_in[2];
    const float* wk = (const float*)d_in[3];
    const float* bk = (const float*)d_in[4];
    const float* wv = (const float*)d_in[5];
    const float* bv = (const float*)d_in[6];
    const float* wo = (const float*)d_in[7];
    const float* bo = (const float*)d_in[8];
    const float* al = (const float*)d_in[9];
    float* out = (float*)d_out;

    cudaFuncSetAttribute(proj_mma, cudaFuncAttributeMaxDynamicSharedMemorySize, PSMEM);
    cudaFuncSetAttribute(attn_mma, cudaFuncAttributeMaxDynamicSharedMemorySize, ASMEM);

    cvt_all<<<8192, 256>>>(x, wq, wk, wv, wo);

    // fused Q/K/V projections (grid.z selects mode 0/1/2)
    proj_mma<<<dim3(DM / 128, MT / 128, 3), 128, PSMEM>>>(bq, bk, bv, 0,
                                                          nullptr, nullptr, nullptr);

    attn_mma<<<dim3(BB * NH, TT / 128), 128, ASMEM>>>();

    // output projection + residual
    proj_mma<<<dim3(DM / 128, MT / 128, 1), 128, PSMEM>>>(bo, bo, bo, 3,
                                                          x, al, out);
}

// round 13
// speedup vs baseline: 1.0527x; 1.0527x over previous
#include <cuda_runtime.h>
#include <cuda_bf16.h>
#include <math.h>

#define TT 2048
#define DM 1024
#define NH 16
#define HDI 64
#define BB 2
#define MT (BB*TT)     // 4096
#define GS 40          // proj smem stride (bf16): 80B/row -> conflict-free ldmatrix

// proj pipeline: 4 stages, each A(10240B)+B(10240B)
#define PSTG 20480
#define PSMEM (4*PSTG)
// attn pipeline: 3 stages, each K(18432B)+V(18432B); Q staged via stage2 K region
#define ASTG 36864
#define ASMEM (3*ASTG)

typedef __nv_bfloat16 bf16;
typedef __nv_bfloat162 bf162;

// ---------------- scratch (__device__ globals; no allocation) ----------------
__device__ bf16 g_Xb[MT*DM];              // x in bf16
__device__ bf16 g_Wb[4][DM*DM];           // weights bf16 (q,k,v,o)
__device__ bf16 g_Qb[BB*NH*TT*HDI];       // per-head [B,H,T,64]
__device__ bf16 g_Kb[BB*NH*TT*HDI];
__device__ bf16 g_Vb[BB*NH*TT*HDI];
__device__ bf16 g_Ob[MT*DM];              // attn out [B,T,D] bf16 (A of out-proj)

// ---------------- helpers ----------------
__device__ __forceinline__ unsigned pack2(float a, float b) {
    bf162 t = __floats2bfloat162_rn(a, b);
    return *reinterpret_cast<unsigned*>(&t);
}
__device__ __forceinline__ void st2(bf16* p, bf16 a, bf16 b) {
    bf162 t; t.x = a; t.y = b;
    *reinterpret_cast<bf162*>(p) = t;
}
__device__ __forceinline__ void mma16816(float* c,
    unsigned a0, unsigned a1, unsigned a2, unsigned a3, unsigned b0, unsigned b1) {
    asm volatile(
        "mma.sync.aligned.m16n8k16.row.col.f32.bf16.bf16.f32 "
        "{%0,%1,%2,%3},{%4,%5,%6,%7},{%8,%9},{%0,%1,%2,%3};\n"
        : "+f"(c[0]), "+f"(c[1]), "+f"(c[2]), "+f"(c[3])
        : "r"(a0), "r"(a1), "r"(a2), "r"(a3), "r"(b0), "r"(b1));
}
__device__ __forceinline__ void ldsm4(unsigned& r0, unsigned& r1, unsigned& r2, unsigned& r3, unsigned addr) {
    asm volatile("ldmatrix.sync.aligned.m8n8.x4.shared.b16 {%0,%1,%2,%3},[%4];\n"
        : "=r"(r0), "=r"(r1), "=r"(r2), "=r"(r3) : "r"(addr));
}
__device__ __forceinline__ void ldsm4t(unsigned& r0, unsigned& r1, unsigned& r2, unsigned& r3, unsigned addr) {
    asm volatile("ldmatrix.sync.aligned.m8n8.x4.trans.shared.b16 {%0,%1,%2,%3},[%4];\n"
        : "=r"(r0), "=r"(r1), "=r"(r2), "=r"(r3) : "r"(addr));
}
__device__ __forceinline__ void cpa16(unsigned dst, const void* src) {
    asm volatile("cp.async.cg.shared.global [%0], [%1], 16;" :: "r"(dst), "l"(src));
}
#define CP_COMMIT() asm volatile("cp.async.commit_group;")
#define CP_WAIT2()  asm volatile("cp.async.wait_group 2;")
#define CP_WAIT1()  asm volatile("cp.async.wait_group 1;")
#define CP_WAIT0()  asm volatile("cp.async.wait_group 0;")

// sigmoid(s/8) = 0.5*tanh(s/16)+0.5  (single MUFU via tanh.approx)
__device__ __forceinline__ float sigm8(float s) {
    float t;
    asm("tanh.approx.f32 %0, %1;" : "=f"(t) : "f"(s * 0.0625f));
    return fmaf(t, 0.5f, 0.5f);
}

// ---------------- fp32 -> bf16, MLP=4 per thread (16 floats) ----------------
// 2048 blocks x 256 threads x 16 floats = 8M floats.
// blocks 0..1023: x (4M). 1024..2047: wq/wk/wv/wo (1M each, 256 blocks each).
__global__ void cvt_all(const float* __restrict__ x,
                        const float* __restrict__ wq, const float* __restrict__ wk,
                        const float* __restrict__ wv, const float* __restrict__ wo)
{
    int b = blockIdx.x;
    const float* src;
    bf16* dst;
    if (b < 1024) {
        src = x + (size_t)b * 4096;
        dst = g_Xb + (size_t)b * 4096;
    } else {
        int w = (b - 1024) >> 8, r = (b - 1024) & 255;
        src = ((w == 0) ? wq : (w == 1) ? wk : (w == 2) ? wv : wo) + (size_t)r * 4096;
        dst = g_Wb[w] + (size_t)r * 4096;
    }
    const int t4 = threadIdx.x * 4;
    float4 v0 = *(const float4*)(src + t4);
    float4 v1 = *(const float4*)(src + 1024 + t4);
    float4 v2 = *(const float4*)(src + 2048 + t4);
    float4 v3 = *(const float4*)(src + 3072 + t4);
    uint2 o;
    o.x = pack2(v0.x, v0.y); o.y = pack2(v0.z, v0.w);
    *(uint2*)(dst + t4) = o;
    o.x = pack2(v1.x, v1.y); o.y = pack2(v1.z, v1.w);
    *(uint2*)(dst + 1024 + t4) = o;
    o.x = pack2(v2.x, v2.y); o.y = pack2(v2.z, v2.w);
    *(uint2*)(dst + 2048 + t4) = o;
    o.x = pack2(v3.x, v3.y); o.y = pack2(v3.z, v3.w);
    *(uint2*)(dst + 3072 + t4) = o;
}

// ---------------- projection GEMM: 4 warps, warp tile 64x64 (R11, fastest) ----------------
// C[M=4096,N=1024] = A[M,1024] . W[N,1024]^T (+bias)
// grid.z + base_mode -> mode. 0/1/2: per-head Q/K/V; 3: out = x + alpha*(C+bias)
__global__ __launch_bounds__(128, 2) void proj_mma(
    const float* __restrict__ b0p, const float* __restrict__ b1p,
    const float* __restrict__ b2p, int base_mode,
    const float* __restrict__ xres, const float* __restrict__ alphap,
    float* __restrict__ outf)
{
    extern __shared__ char smraw[];
    const int tid  = threadIdx.x;
    const int lane = tid & 31, wid = tid >> 5;
    const int wm = wid >> 1, wn = wid & 1;       // 2x2 warps; warp tile 64x64
    const int mode = base_mode + blockIdx.z;
    const float* bias = (blockIdx.z == 0) ? b0p : (blockIdx.z == 1) ? b1p : b2p;
    const int bm = blockIdx.y * 128, bn = blockIdx.x * 128;

    const bf16* A = (mode == 3) ? g_Ob : g_Xb;
    const bf16* W = g_Wb[mode];
    const bf16* Ag = A + (size_t)bm * DM;
    const bf16* Wg = W + (size_t)bn * DM;

    unsigned sb = (unsigned)__cvta_generic_to_shared(smraw);

    // issue k-chunk kt into stage s (512 16B chunks per matrix; 4+4 per thread)
    auto issue = [&](int kt, int s) {
        const unsigned dA = sb + (unsigned)s * PSTG;
        const unsigned dB = dA + 10240;
        const int koff = kt * 32;
        #pragma unroll
        for (int i = 0; i < 4; i++) {
            int e = tid + i * 128;
            int row = e >> 2, c16 = e & 3;
            cpa16(dA + row * 80 + c16 * 16, Ag + (size_t)row * DM + koff + c16 * 8);
            cpa16(dB + row * 80 + c16 * 16, Wg + (size_t)row * DM + koff + c16 * 8);
        }
        CP_COMMIT();
    };

    float c[4][8][4];
    #pragma unroll
    for (int i = 0; i < 4; i++)
        #pragma unroll
        for (int j = 0; j < 8; j++)
            #pragma unroll
            for (int q = 0; q < 4; q++) c[i][j][q] = 0.f;

    const int a_row  = lane & 15;
    const int a_coff = (lane >> 4) << 3;
    const int b_row  = (lane & 7) + ((lane >> 4) << 3);
    const int b_coff = lane & 8;

    issue(0, 0);
    issue(1, 1);
    issue(2, 2);

    for (int kt = 0; kt < 32; kt++) {
        if (kt < 30) CP_WAIT2();
        else if (kt == 30) CP_WAIT1();
        else CP_WAIT0();
        __syncthreads();
        if (kt + 3 < 32) issue(kt + 3, (kt + 3) & 3);

        const unsigned cA = sb + (unsigned)(kt & 3) * PSTG;
        const unsigned cB = cA + 10240;
        #pragma unroll
        for (int d = 0; d < 32; d += 16) {
            unsigned af[4][4];
            #pragma unroll
            for (int mi = 0; mi < 4; mi++)
                ldsm4(af[mi][0], af[mi][1], af[mi][2], af[mi][3],
                      cA + (unsigned)(((wm * 64 + mi * 16 + a_row) * GS + d + a_coff) * 2));
            #pragma unroll
            for (int np = 0; np < 4; np++) {
                unsigned b0, b1, b2, b3;
                ldsm4(b0, b1, b2, b3,
                      cB + (unsigned)(((wn * 64 + np * 16 + b_row) * GS + d + b_coff) * 2));
                #pragma unroll
                for (int mi = 0; mi < 4; mi++) {
                    mma16816(c[mi][np * 2],     af[mi][0], af[mi][1], af[mi][2], af[mi][3], b0, b1);
                    mma16816(c[mi][np * 2 + 1], af[mi][0], af[mi][1], af[mi][2], af[mi][3], b2, b3);
                }
            }
        }
    }

    // epilogue
    const int g  = lane >> 2;
    const int q2 = (lane & 3) * 2;
    if (mode == 3) {
        const float alpha = *alphap;
        #pragma unroll
        for (int mi = 0; mi < 4; mi++)
            #pragma unroll
            for (int half = 0; half < 2; half++) {
                int m = bm + wm * 64 + mi * 16 + g + half * 8;
                #pragma unroll
                for (int ni = 0; ni < 8; ni++) {
                    int n = bn + wn * 64 + ni * 8 + q2;
                    float2 o;
                    o.x = xres[(size_t)m * DM + n]     + alpha * (c[mi][ni][half * 2 + 0] + bias[n]);
                    o.y = xres[(size_t)m * DM + n + 1] + alpha * (c[mi][ni][half * 2 + 1] + bias[n + 1]);
                    *(float2*)&outf[(size_t)m * DM + n] = o;
                }
            }
    } else {
        bf16* outp = (mode == 0) ? g_Qb : (mode == 1) ? g_Kb : g_Vb;
        #pragma unroll
        for (int mi = 0; mi < 4; mi++)
            #pragma unroll
            for (int half = 0; half < 2; half++) {
                int m = bm + wm * 64 + mi * 16 + g + half * 8;
                int b_ = m >> 11, t_ = m & 2047;
                #pragma unroll
                for (int ni = 0; ni < 8; ni++) {
                    int n = bn + wn * 64 + ni * 8 + q2;
                    int h = n >> 6, hd = n & 63;
                    size_t rb = ((size_t)(b_ * NH + h) * TT + t_);
                    float v0 = c[mi][ni][half * 2 + 0] + bias[n];
                    float v1 = c[mi][ni][half * 2 + 1] + bias[n + 1];
                    st2(&outp[rb * 64 + hd],
                        __float2bfloat16_rn(v0), __float2bfloat16_rn(v1));
                }
            }
    }
}

// ---------------- attention (R10 config: 8 warps x 16 q-rows, 3-stage cp.async) ----------------
// CTA = (b*H+h, 128-q tile); Q in regs, 1 barrier/iter.
__global__ __launch_bounds__(256, 2) void attn_mma()
{
    extern __shared__ char smraw[];
    const int tid = threadIdx.x, lane = tid & 31, wid = tid >> 5;
    const int bh = blockIdx.x, qt = blockIdx.y;
    const bf16* Qg = g_Qb + (size_t)(bh * TT + qt * 128) * 64;
    const bf16* Kg = g_Kb + (size_t)bh * TT * 64;
    const bf16* Vg = g_Vb + (size_t)bh * TT * 64;

    unsigned sb = (unsigned)__cvta_generic_to_shared(smraw);

    // issue K/V tile t into stage s
    auto issueKV = [&](int t, int s) {
        const bf16* Kt = Kg + (size_t)t * 128 * 64;
        const bf16* Vt = Vg + (size_t)t * 128 * 64;
        const unsigned dK = sb + (unsigned)s * ASTG;
        const unsigned dV = dK + 18432;
        #pragma unroll
        for (int i = 0; i < 4; i++) {
            int e = tid + i * 256;
            int row = e >> 3, c16 = e & 7;
            cpa16(dK + row * 144 + c16 * 16, Kt + (size_t)row * 64 + c16 * 8);
            cpa16(dV + row * 144 + c16 * 16, Vt + (size_t)row * 64 + c16 * 8);
        }
        CP_COMMIT();
    };

    // prologue: tiles 0,1 into stages 0,1; Q into stage2's K region
    issueKV(0, 0);
    issueKV(1, 1);
    {
        const unsigned dQ = sb + 2u * ASTG;
        #pragma unroll
        for (int i = 0; i < 4; i++) {
            int e = tid + i * 256;
            int row = e >> 3, c16 = e & 7;
            cpa16(dQ + row * 144 + c16 * 16, Qg + (size_t)row * 64 + c16 * 8);
        }
        CP_COMMIT();
    }

    const int a_row  = lane & 15;
    const int a_coff = (lane >> 4) << 3;
    const int b_row  = (lane & 7) + ((lane >> 4) << 3);
    const int b_coff = lane & 8;
    const int v_row  = (lane & 7) + (lane & 8);
    const int v_coff = (lane >> 4) << 3;
    const int qr = wid * 16;

    CP_WAIT0();
    __syncthreads();

    // hoist Q fragments to registers (stage2 K region gets recycled at kt=0)
    unsigned qf[4][4];
    #pragma unroll
    for (int d16 = 0; d16 < 4; d16++)
        ldsm4(qf[d16][0], qf[d16][1], qf[d16][2], qf[d16][3],
              sb + 2u * ASTG + (unsigned)(((qr + a_row) * 144) + (d16 * 16 + a_coff) * 2));

    float oc[8][4];
    #pragma unroll
    for (int i = 0; i < 8; i++)
        #pragma unroll
        for (int j = 0; j < 4; j++) oc[i][j] = 0.f;
    float ds0 = 0.f, ds1 = 0.f;

    for (int kt = 0; kt < 16; kt++) {
        if (kt == 15) CP_WAIT0(); else CP_WAIT1();
        __syncthreads();
        if (kt + 2 < 16) issueKV(kt + 2, (kt + 2) % 3);

        const unsigned cK = sb + (unsigned)(kt % 3) * ASTG;
        const unsigned cV = cK + 18432;

        #pragma unroll
        for (int half = 0; half < 2; half++) {
            float sc[8][4];
            #pragma unroll
            for (int i = 0; i < 8; i++)
                #pragma unroll
                for (int j = 0; j < 4; j++) sc[i][j] = 0.f;

            #pragma unroll
            for (int np = 0; np < 4; np++) {
                const int npg = half * 4 + np;
                #pragma unroll
                for (int d16 = 0; d16 < 4; d16++) {
                    unsigned b0, b1, b2, b3;
                    ldsm4(b0, b1, b2, b3,
                          cK + (unsigned)(((npg * 16 + b_row) * 144) + (d16 * 16 + b_coff) * 2));
                    mma16816(sc[np * 2],     qf[d16][0], qf[d16][1], qf[d16][2], qf[d16][3], b0, b1);
                    mma16816(sc[np * 2 + 1], qf[d16][0], qf[d16][1], qf[d16][2], qf[d16][3], b2, b3);
                }
            }

            #pragma unroll
            for (int nt = 0; nt < 8; nt++) {
                float g0 = sigm8(sc[nt][0]);
                float g1 = sigm8(sc[nt][1]);
                float g2 = sigm8(sc[nt][2]);
                float g3 = sigm8(sc[nt][3]);
                sc[nt][0] = g0; sc[nt][1] = g1; sc[nt][2] = g2; sc[nt][3] = g3;
                ds0 += g0 + g1;
                ds1 += g2 + g3;
            }

            #pragma unroll
            for (int t = 0; t < 4; t++) {
                const int tg = half * 4 + t;
                unsigned a0 = pack2(sc[2 * t][0],     sc[2 * t][1]);
                unsigned a1 = pack2(sc[2 * t][2],     sc[2 * t][3]);
                unsigned a2 = pack2(sc[2 * t + 1][0], sc[2 * t + 1][1]);
                unsigned a3 = pack2(sc[2 * t + 1][2], sc[2 * t + 1][3]);
                #pragma unroll
                for (int nq = 0; nq < 4; nq++) {
                    unsigned b0, b1, b2, b3;
                    ldsm4t(b0, b1, b2, b3,
                           cV + (unsigned)(((tg * 16 + v_row) * 144) + (nq * 16 + v_coff) * 2));
                    mma16816(oc[nq * 2],     a0, a1, a2, a3, b0, b1);
                    mma16816(oc[nq * 2 + 1], a0, a1, a2, a3, b2, b3);
                }
            }
        }
    }

    // denominator reduce across the quad
    ds0 += __shfl_xor_sync(0xffffffffu, ds0, 1);
    ds0 += __shfl_xor_sync(0xffffffffu, ds0, 2);
    ds1 += __shfl_xor_sync(0xffffffffu, ds1, 1);
    ds1 += __shfl_xor_sync(0xffffffffu, ds1, 2);
    const float inv0 = 1.f / (ds0 + 1e-6f);
    const float inv1 = 1.f / (ds1 + 1e-6f);

    // epilogue: normalized O -> g_Ob [B,T,D] bf16
    const int b_ = bh >> 4, h = bh & 15;
    const int g = lane >> 2, q2 = (lane & 3) * 2;
    const int t0 = qt * 128 + qr + g;
    const size_t r0 = (size_t)(b_ * TT + t0) * DM + h * 64;
    const size_t r1 = r0 + (size_t)8 * DM;
    #pragma unroll
    for (int nt = 0; nt < 8; nt++) {
        int hd = nt * 8 + q2;
        st2(&g_Ob[r0 + hd], __float2bfloat16_rn(oc[nt][0] * inv0),
                            __float2bfloat16_rn(oc[nt][1] * inv0));
        st2(&g_Ob[r1 + hd], __float2bfloat16_rn(oc[nt][2] * inv1),
                            __float2bfloat16_rn(oc[nt][3] * inv1));
    }
}

// ---------------------------------------------------------------------------
extern "C" void kernel_launch(void* const* d_in, const int* in_sizes, int n_in,
                              void* d_out, int out_size)
{
    const float* x  = (const float*)d_in[0];
    const float* wq = (const float*)d_in[1];
    const float* bq = (const float*)d_in[2];
    const float* wk = (const float*)d_in[3];
    const float* bk = (const float*)d_in[4];
    const float* wv = (const float*)d_in[5];
    const float* bv = (const float*)d_in[6];
    const float* wo = (const float*)d_in[7];
    const float* bo = (const float*)d_in[8];
    const float* al = (const float*)d_in[9];
    float* out = (float*)d_out;

    cudaFuncSetAttribute(proj_mma, cudaFuncAttributeMaxDynamicSharedMemorySize, PSMEM);
    cudaFuncSetAttribute(attn_mma, cudaFuncAttributeMaxDynamicSharedMemorySize, ASMEM);

    cvt_all<<<2048, 256>>>(x, wq, wk, wv, wo);

    // fused Q/K/V projections (grid.z selects mode 0/1/2)
    proj_mma<<<dim3(DM / 128, MT / 128, 3), 128, PSMEM>>>(bq, bk, bv, 0,
                                                          nullptr, nullptr, nullptr);

    attn_mma<<<dim3(BB * NH, TT / 128), 256, ASMEM>>>();

    // output projection + residual
    proj_mma<<<dim3(DM / 128, MT / 128, 1), 128, PSMEM>>>(bo, bo, bo, 3,
                                                          x, al, out);
}

// round 14
// speedup vs baseline: 1.1280x; 1.0715x over previous
#include <cuda_runtime.h>
#include <cuda_bf16.h>
#include <cuda_fp16.h>
#include <math.h>

#define TT 2048
#define DM 1024
#define NH 16
#define HDI 64
#define BB 2
#define MT (BB*TT)     // 4096
#define GS 40          // proj smem stride (bf16): 80B/row -> conflict-free ldmatrix

// proj pipeline: 4 stages, each A(10240B)+B(10240B)
#define PSTG 20480
#define PSMEM (4*PSTG)
// attn pipeline: 3 stages, each K(18432B)+V(18432B); Q staged via stage2 K region
#define ASTG 36864
#define ASMEM (3*ASTG)

typedef __nv_bfloat16 bf16;
typedef __nv_bfloat162 bf162;

// ---------------- scratch (__device__ globals; no allocation) ----------------
__device__ bf16  g_Xb[MT*DM];             // x in bf16
__device__ bf16  g_Wb[4][DM*DM];          // weights bf16 (q,k,v,o)
__device__ bf16  g_Qb[BB*NH*TT*HDI];      // per-head [B,H,T,64]
__device__ bf16  g_Kb[BB*NH*TT*HDI];
__device__ __half g_Vh[BB*NH*TT*HDI];     // V in f16 (PV runs f16 MMA)
__device__ bf16  g_Ob[MT*DM];             // attn out [B,T,D] bf16 (A of out-proj)

// ---------------- helpers ----------------
__device__ __forceinline__ unsigned pack2(float a, float b) {
    bf162 t = __floats2bfloat162_rn(a, b);
    return *reinterpret_cast<unsigned*>(&t);
}
__device__ __forceinline__ void st2(bf16* p, bf16 a, bf16 b) {
    bf162 t; t.x = a; t.y = b;
    *reinterpret_cast<bf162*>(p) = t;
}
// bf16 x bf16 -> f32 MMA
__device__ __forceinline__ void mma16816(float* c,
    unsigned a0, unsigned a1, unsigned a2, unsigned a3, unsigned b0, unsigned b1) {
    asm volatile(
        "mma.sync.aligned.m16n8k16.row.col.f32.bf16.bf16.f32 "
        "{%0,%1,%2,%3},{%4,%5,%6,%7},{%8,%9},{%0,%1,%2,%3};\n"
        : "+f"(c[0]), "+f"(c[1]), "+f"(c[2]), "+f"(c[3])
        : "r"(a0), "r"(a1), "r"(a2), "r"(a3), "r"(b0), "r"(b1));
}
// f16 x f16 -> f32 MMA (PV + denominator)
__device__ __forceinline__ void mma16816h(float* c,
    unsigned a0, unsigned a1, unsigned a2, unsigned a3, unsigned b0, unsigned b1) {
    asm volatile(
        "mma.sync.aligned.m16n8k16.row.col.f32.f16.f16.f32 "
        "{%0,%1,%2,%3},{%4,%5,%6,%7},{%8,%9},{%0,%1,%2,%3};\n"
        : "+f"(c[0]), "+f"(c[1]), "+f"(c[2]), "+f"(c[3])
        : "r"(a0), "r"(a1), "r"(a2), "r"(a3), "r"(b0), "r"(b1));
}
__device__ __forceinline__ void ldsm4(unsigned& r0, unsigned& r1, unsigned& r2, unsigned& r3, unsigned addr) {
    asm volatile("ldmatrix.sync.aligned.m8n8.x4.shared.b16 {%0,%1,%2,%3},[%4];\n"
        : "=r"(r0), "=r"(r1), "=r"(r2), "=r"(r3) : "r"(addr));
}
__device__ __forceinline__ void ldsm4t(unsigned& r0, unsigned& r1, unsigned& r2, unsigned& r3, unsigned addr) {
    asm volatile("ldmatrix.sync.aligned.m8n8.x4.trans.shared.b16 {%0,%1,%2,%3},[%4];\n"
        : "=r"(r0), "=r"(r1), "=r"(r2), "=r"(r3) : "r"(addr));
}
__device__ __forceinline__ void cpa16(unsigned dst, const void* src) {
    asm volatile("cp.async.cg.shared.global [%0], [%1], 16;" :: "r"(dst), "l"(src));
}
#define CP_COMMIT() asm volatile("cp.async.commit_group;")
#define CP_WAIT2()  asm volatile("cp.async.wait_group 2;")
#define CP_WAIT1()  asm volatile("cp.async.wait_group 1;")
#define CP_WAIT0()  asm volatile("cp.async.wait_group 0;")

// gate pair: sigmoid((lo,hi)/8) in f16x2 = MMA A-fragment directly.
// cvt f32x2->f16x2, *2^-4 (exact), tanh.approx.f16x2, 0.5*t+0.5.
__device__ __forceinline__ unsigned gate2(float lo, float hi) {
    unsigned h, s, t, p;
    asm("cvt.rn.f16x2.f32 %0, %1, %2;" : "=r"(h) : "f"(hi), "f"(lo));
    asm("mul.rn.f16x2 %0, %1, %2;" : "=r"(s) : "r"(h), "r"(0x2C002C00u));   // *0.0625
    asm("tanh.approx.f16x2 %0, %1;" : "=r"(t) : "r"(s));
    asm("fma.rn.f16x2 %0, %1, %2, %3;" : "=r"(p)
        : "r"(t), "r"(0x38003800u), "r"(0x38003800u));                      // 0.5*t+0.5
    return p;
}
#define ONES_H2 0x3C003C00u

// ---------------- fp32 -> bf16, MLP=4 per thread (16 floats) ----------------
__global__ void cvt_all(const float* __restrict__ x,
                        const float* __restrict__ wq, const float* __restrict__ wk,
                        const float* __restrict__ wv, const float* __restrict__ wo)
{
    int b = blockIdx.x;
    const float* src;
    bf16* dst;
    if (b < 1024) {
        src = x + (size_t)b * 4096;
        dst = g_Xb + (size_t)b * 4096;
    } else {
        int w = (b - 1024) >> 8, r = (b - 1024) & 255;
        src = ((w == 0) ? wq : (w == 1) ? wk : (w == 2) ? wv : wo) + (size_t)r * 4096;
        dst = g_Wb[w] + (size_t)r * 4096;
    }
    const int t4 = threadIdx.x * 4;
    float4 v0 = *(const float4*)(src + t4);
    float4 v1 = *(const float4*)(src + 1024 + t4);
    float4 v2 = *(const float4*)(src + 2048 + t4);
    float4 v3 = *(const float4*)(src + 3072 + t4);
    uint2 o;
    o.x = pack2(v0.x, v0.y); o.y = pack2(v0.z, v0.w);
    *(uint2*)(dst + t4) = o;
    o.x = pack2(v1.x, v1.y); o.y = pack2(v1.z, v1.w);
    *(uint2*)(dst + 1024 + t4) = o;
    o.x = pack2(v2.x, v2.y); o.y = pack2(v2.z, v2.w);
    *(uint2*)(dst + 2048 + t4) = o;
    o.x = pack2(v3.x, v3.y); o.y = pack2(v3.z, v3.w);
    *(uint2*)(dst + 3072 + t4) = o;
}

// ---------------- projection GEMM: 4 warps, warp tile 64x64 ----------------
__global__ __launch_bounds__(128, 2) void proj_mma(
    const float* __restrict__ b0p, const float* __restrict__ b1p,
    const float* __restrict__ b2p, int base_mode,
    const float* __restrict__ xres, const float* __restrict__ alphap,
    float* __restrict__ outf)
{
    extern __shared__ char smraw[];
    const int tid  = threadIdx.x;
    const int lane = tid & 31, wid = tid >> 5;
    const int wm = wid >> 1, wn = wid & 1;       // 2x2 warps; warp tile 64x64
    const int mode = base_mode + blockIdx.z;
    const float* bias = (blockIdx.z == 0) ? b0p : (blockIdx.z == 1) ? b1p : b2p;
    const int bm = blockIdx.y * 128, bn = blockIdx.x * 128;

    const bf16* A = (mode == 3) ? g_Ob : g_Xb;
    const bf16* W = g_Wb[mode];
    const bf16* Ag = A + (size_t)bm * DM;
    const bf16* Wg = W + (size_t)bn * DM;

    unsigned sb = (unsigned)__cvta_generic_to_shared(smraw);

    auto issue = [&](int kt, int s) {
        const unsigned dA = sb + (unsigned)s * PSTG;
        const unsigned dB = dA + 10240;
        const int koff = kt * 32;
        #pragma unroll
        for (int i = 0; i < 4; i++) {
            int e = tid + i * 128;
            int row = e >> 2, c16 = e & 3;
            cpa16(dA + row * 80 + c16 * 16, Ag + (size_t)row * DM + koff + c16 * 8);
            cpa16(dB + row * 80 + c16 * 16, Wg + (size_t)row * DM + koff + c16 * 8);
        }
        CP_COMMIT();
    };

    float c[4][8][4];
    #pragma unroll
    for (int i = 0; i < 4; i++)
        #pragma unroll
        for (int j = 0; j < 8; j++)
            #pragma unroll
            for (int q = 0; q < 4; q++) c[i][j][q] = 0.f;

    const int a_row  = lane & 15;
    const int a_coff = (lane >> 4) << 3;
    const int b_row  = (lane & 7) + ((lane >> 4) << 3);
    const int b_coff = lane & 8;

    issue(0, 0);
    issue(1, 1);
    issue(2, 2);

    for (int kt = 0; kt < 32; kt++) {
        if (kt < 30) CP_WAIT2();
        else if (kt == 30) CP_WAIT1();
        else CP_WAIT0();
        __syncthreads();
        if (kt + 3 < 32) issue(kt + 3, (kt + 3) & 3);

        const unsigned cA = sb + (unsigned)(kt & 3) * PSTG;
        const unsigned cB = cA + 10240;
        #pragma unroll
        for (int d = 0; d < 32; d += 16) {
            unsigned af[4][4];
            #pragma unroll
            for (int mi = 0; mi < 4; mi++)
                ldsm4(af[mi][0], af[mi][1], af[mi][2], af[mi][3],
                      cA + (unsigned)(((wm * 64 + mi * 16 + a_row) * GS + d + a_coff) * 2));
            #pragma unroll
            for (int np = 0; np < 4; np++) {
                unsigned b0, b1, b2, b3;
                ldsm4(b0, b1, b2, b3,
                      cB + (unsigned)(((wn * 64 + np * 16 + b_row) * GS + d + b_coff) * 2));
                #pragma unroll
                for (int mi = 0; mi < 4; mi++) {
                    mma16816(c[mi][np * 2],     af[mi][0], af[mi][1], af[mi][2], af[mi][3], b0, b1);
                    mma16816(c[mi][np * 2 + 1], af[mi][0], af[mi][1], af[mi][2], af[mi][3], b2, b3);
                }
            }
        }
    }

    // epilogue
    const int g  = lane >> 2;
    const int q2 = (lane & 3) * 2;
    if (mode == 3) {
        const float alpha = *alphap;
        #pragma unroll
        for (int mi = 0; mi < 4; mi++)
            #pragma unroll
            for (int half = 0; half < 2; half++) {
                int m = bm + wm * 64 + mi * 16 + g + half * 8;
                #pragma unroll
                for (int ni = 0; ni < 8; ni++) {
                    int n = bn + wn * 64 + ni * 8 + q2;
                    float2 o;
                    o.x = xres[(size_t)m * DM + n]     + alpha * (c[mi][ni][half * 2 + 0] + bias[n]);
                    o.y = xres[(size_t)m * DM + n + 1] + alpha * (c[mi][ni][half * 2 + 1] + bias[n + 1]);
                    *(float2*)&outf[(size_t)m * DM + n] = o;
                }
            }
    } else {
        #pragma unroll
        for (int mi = 0; mi < 4; mi++)
            #pragma unroll
            for (int half = 0; half < 2; half++) {
                int m = bm + wm * 64 + mi * 16 + g + half * 8;
                int b_ = m >> 11, t_ = m & 2047;
                #pragma unroll
                for (int ni = 0; ni < 8; ni++) {
                    int n = bn + wn * 64 + ni * 8 + q2;
                    int h = n >> 6, hd = n & 63;
                    size_t rb = ((size_t)(b_ * NH + h) * TT + t_);
                    float v0 = c[mi][ni][half * 2 + 0] + bias[n];
                    float v1 = c[mi][ni][half * 2 + 1] + bias[n + 1];
                    if (mode == 2) {
                        *(__half2*)&g_Vh[rb * 64 + hd] = __floats2half2_rn(v0, v1);
                    } else {
                        bf16* outp = (mode == 0) ? g_Qb : g_Kb;
                        st2(&outp[rb * 64 + hd],
                            __float2bfloat16_rn(v0), __float2bfloat16_rn(v1));
                    }
                }
            }
    }
}

// ---------------- attention: 8 warps x 16 q-rows, f16x2 gating, denom via ones-MMA ----------------
__global__ __launch_bounds__(256, 2) void attn_mma()
{
    extern __shared__ char smraw[];
    const int tid = threadIdx.x, lane = tid & 31, wid = tid >> 5;
    const int bh = blockIdx.x, qt = blockIdx.y;
    const bf16* Qg = g_Qb + (size_t)(bh * TT + qt * 128) * 64;
    const bf16* Kg = g_Kb + (size_t)bh * TT * 64;
    const __half* Vg = g_Vh + (size_t)bh * TT * 64;

    unsigned sb = (unsigned)__cvta_generic_to_shared(smraw);

    auto issueKV = [&](int t, int s) {
        const bf16*   Kt = Kg + (size_t)t * 128 * 64;
        const __half* Vt = Vg + (size_t)t * 128 * 64;
        const unsigned dK = sb + (unsigned)s * ASTG;
        const unsigned dV = dK + 18432;
        #pragma unroll
        for (int i = 0; i < 4; i++) {
            int e = tid + i * 256;
            int row = e >> 3, c16 = e & 7;
            cpa16(dK + row * 144 + c16 * 16, Kt + (size_t)row * 64 + c16 * 8);
            cpa16(dV + row * 144 + c16 * 16, Vt + (size_t)row * 64 + c16 * 8);
        }
        CP_COMMIT();
    };

    issueKV(0, 0);
    issueKV(1, 1);
    {
        const unsigned dQ = sb + 2u * ASTG;
        #pragma unroll
        for (int i = 0; i < 4; i++) {
            int e = tid + i * 256;
            int row = e >> 3, c16 = e & 7;
            cpa16(dQ + row * 144 + c16 * 16, Qg + (size_t)row * 64 + c16 * 8);
        }
        CP_COMMIT();
    }

    const int a_row  = lane & 15;
    const int a_coff = (lane >> 4) << 3;
    const int b_row  = (lane & 7) + ((lane >> 4) << 3);
    const int b_coff = lane & 8;
    const int v_row  = (lane & 7) + (lane & 8);
    const int v_coff = (lane >> 4) << 3;
    const int qr = wid * 16;

    CP_WAIT0();
    __syncthreads();

    unsigned qf[4][4];
    #pragma unroll
    for (int d16 = 0; d16 < 4; d16++)
        ldsm4(qf[d16][0], qf[d16][1], qf[d16][2], qf[d16][3],
              sb + 2u * ASTG + (unsigned)(((qr + a_row) * 144) + (d16 * 16 + a_coff) * 2));

    float oc[8][4];
    #pragma unroll
    for (int i = 0; i < 8; i++)
        #pragma unroll
        for (int j = 0; j < 4; j++) oc[i][j] = 0.f;
    float dc[4] = {0.f, 0.f, 0.f, 0.f};   // denominator row-sums via ones-MMA

    for (int kt = 0; kt < 16; kt++) {
        if (kt == 15) CP_WAIT0(); else CP_WAIT1();
        __syncthreads();
        if (kt + 2 < 16) issueKV(kt + 2, (kt + 2) % 3);

        const unsigned cK = sb + (unsigned)(kt % 3) * ASTG;
        const unsigned cV = cK + 18432;

        #pragma unroll
        for (int half = 0; half < 2; half++) {
            float sc[8][4];
            #pragma unroll
            for (int i = 0; i < 8; i++)
                #pragma unroll
                for (int j = 0; j < 4; j++) sc[i][j] = 0.f;

            #pragma unroll
            for (int np = 0; np < 4; np++) {
                const int npg = half * 4 + np;
                #pragma unroll
                for (int d16 = 0; d16 < 4; d16++) {
                    unsigned b0, b1, b2, b3;
                    ldsm4(b0, b1, b2, b3,
                          cK + (unsigned)(((npg * 16 + b_row) * 144) + (d16 * 16 + b_coff) * 2));
                    mma16816(sc[np * 2],     qf[d16][0], qf[d16][1], qf[d16][2], qf[d16][3], b0, b1);
                    mma16816(sc[np * 2 + 1], qf[d16][0], qf[d16][1], qf[d16][2], qf[d16][3], b2, b3);
                }
            }

            // gate (f16x2) -> A fragments; denominator + PV on tensor pipe
            #pragma unroll
            for (int t = 0; t < 4; t++) {
                const int tg = half * 4 + t;
                unsigned a0 = gate2(sc[2 * t][0],     sc[2 * t][1]);
                unsigned a1 = gate2(sc[2 * t][2],     sc[2 * t][3]);
                unsigned a2 = gate2(sc[2 * t + 1][0], sc[2 * t + 1][1]);
                unsigned a3 = gate2(sc[2 * t + 1][2], sc[2 * t + 1][3]);
                mma16816h(dc, a0, a1, a2, a3, ONES_H2, ONES_H2);   // row sums of P-chunk
                #pragma unroll
                for (int nq = 0; nq < 4; nq++) {
                    unsigned b0, b1, b2, b3;
                    ldsm4t(b0, b1, b2, b3,
                           cV + (unsigned)(((tg * 16 + v_row) * 144) + (nq * 16 + v_coff) * 2));
                    mma16816h(oc[nq * 2],     a0, a1, a2, a3, b0, b1);
                    mma16816h(oc[nq * 2 + 1], a0, a1, a2, a3, b2, b3);
                }
            }
        }
    }

    // dc[0] = row (qr+g) sum, dc[2] = row (qr+g+8) sum — every lane has its own rows
    const float inv0 = 1.f / (dc[0] + 1e-6f);
    const float inv1 = 1.f / (dc[2] + 1e-6f);

    // epilogue: normalized O -> g_Ob [B,T,D] bf16
    const int b_ = bh >> 4, h = bh & 15;
    const int g = lane >> 2, q2 = (lane & 3) * 2;
    const int t0 = qt * 128 + qr + g;
    const size_t r0 = (size_t)(b_ * TT + t0) * DM + h * 64;
    const size_t r1 = r0 + (size_t)8 * DM;
    #pragma unroll
    for (int nt = 0; nt < 8; nt++) {
        int hd = nt * 8 + q2;
        st2(&g_Ob[r0 + hd], __float2bfloat16_rn(oc[nt][0] * inv0),
                            __float2bfloat16_rn(oc[nt][1] * inv0));
        st2(&g_Ob[r1 + hd], __float2bfloat16_rn(oc[nt][2] * inv1),
                            __float2bfloat16_rn(oc[nt][3] * inv1));
    }
}

// ---------------------------------------------------------------------------
extern "C" void kernel_launch(void* const* d_in, const int* in_sizes, int n_in,
                              void* d_out, int out_size)
{
    const float* x  = (const float*)d_in[0];
    const float* wq = (const float*)d_in[1];
    const float* bq = (const float*)d_in[2];
    const float* wk = (const float*)d_in[3];
    const float* bk = (const float*)d_in[4];
    const float* wv = (const float*)d_in[5];
    const float* bv = (const float*)d_in[6];
    const float* wo = (const float*)d_in[7];
    const float* bo = (const float*)d_in[8];
    const float* al = (const float*)d_in[9];
    float* out = (float*)d_out;

    cudaFuncSetAttribute(proj_mma, cudaFuncAttributeMaxDynamicSharedMemorySize, PSMEM);
    cudaFuncSetAttribute(attn_mma, cudaFuncAttributeMaxDynamicSharedMemorySize, ASMEM);

    cvt_all<<<2048, 256>>>(x, wq, wk, wv, wo);

    // fused Q/K/V projections (grid.z selects mode 0/1/2)
    proj_mma<<<dim3(DM / 128, MT / 128, 3), 128, PSMEM>>>(bq, bk, bv, 0,
                                                          nullptr, nullptr, nullptr);

    attn_mma<<<dim3(BB * NH, TT / 128), 256, ASMEM>>>();

    // output projection + residual
    proj_mma<<<dim3(DM / 128, MT / 128, 1), 128, PSMEM>>>(bo, bo, bo, 3,
                                                          x, al, out);
}

// round 15
// speedup vs baseline: 1.1490x; 1.0187x over previous
#include <cuda_runtime.h>
#include <cuda_fp16.h>
#include <math.h>

#define TT 2048
#define DM 1024
#define NH 16
#define HDI 64
#define BB 2
#define MT (BB*TT)     // 4096
#define GS 40          // proj smem stride (f16): 80B/row -> conflict-free ldmatrix

// proj pipeline: 3 stages, each A(10240B)+B(10240B); occ 3
#define PSTG 20480
#define PSMEM (3*PSTG)
// attn pipeline: 3 stages, each K(18432B)+V(18432B); Q staged via stage2 K region
#define ASTG 36864
#define ASMEM (3*ASTG)

// ---------------- scratch (__device__ globals; no allocation) ----------------
__device__ __half g_Xh[MT*DM];            // x in f16
__device__ __half g_Wh[4][DM*DM];         // weights f16 (q,k,v,o)
__device__ __half g_Qh[BB*NH*TT*HDI];     // per-head [B,H,T,64]
__device__ __half g_Kh[BB*NH*TT*HDI];
__device__ __half g_Vh[BB*NH*TT*HDI];
__device__ __half g_Oh[MT*DM];            // attn out [B,T,D] f16 (A of out-proj)

// ---------------- helpers ----------------
// f16 x f16 -> f16 MMA (projections + S): C = 2 regs
__device__ __forceinline__ void mma_h(unsigned* c,
    unsigned a0, unsigned a1, unsigned a2, unsigned a3, unsigned b0, unsigned b1) {
    asm volatile(
        "mma.sync.aligned.m16n8k16.row.col.f16.f16.f16.f16 "
        "{%0,%1},{%2,%3,%4,%5},{%6,%7},{%0,%1};\n"
        : "+r"(c[0]), "+r"(c[1])
        : "r"(a0), "r"(a1), "r"(a2), "r"(a3), "r"(b0), "r"(b1));
}
// f16 x f16 -> f32 MMA (PV + denominator)
__device__ __forceinline__ void mma_hf(float* c,
    unsigned a0, unsigned a1, unsigned a2, unsigned a3, unsigned b0, unsigned b1) {
    asm volatile(
        "mma.sync.aligned.m16n8k16.row.col.f32.f16.f16.f32 "
        "{%0,%1,%2,%3},{%4,%5,%6,%7},{%8,%9},{%0,%1,%2,%3};\n"
        : "+f"(c[0]), "+f"(c[1]), "+f"(c[2]), "+f"(c[3])
        : "r"(a0), "r"(a1), "r"(a2), "r"(a3), "r"(b0), "r"(b1));
}
__device__ __forceinline__ void ldsm4(unsigned& r0, unsigned& r1, unsigned& r2, unsigned& r3, unsigned addr) {
    asm volatile("ldmatrix.sync.aligned.m8n8.x4.shared.b16 {%0,%1,%2,%3},[%4];\n"
        : "=r"(r0), "=r"(r1), "=r"(r2), "=r"(r3) : "r"(addr));
}
__device__ __forceinline__ void ldsm4t(unsigned& r0, unsigned& r1, unsigned& r2, unsigned& r3, unsigned addr) {
    asm volatile("ldmatrix.sync.aligned.m8n8.x4.trans.shared.b16 {%0,%1,%2,%3},[%4];\n"
        : "=r"(r0), "=r"(r1), "=r"(r2), "=r"(r3) : "r"(addr));
}
__device__ __forceinline__ void cpa16(unsigned dst, const void* src) {
    asm volatile("cp.async.cg.shared.global [%0], [%1], 16;" :: "r"(dst), "l"(src));
}
#define CP_COMMIT() asm volatile("cp.async.commit_group;")
#define CP_WAIT1()  asm volatile("cp.async.wait_group 1;")
#define CP_WAIT0()  asm volatile("cp.async.wait_group 0;")

// sigmoid(s/8) on a packed f16x2 score reg: *2^-4 (exact), tanh.approx.f16x2, 0.5t+0.5
__device__ __forceinline__ unsigned gate2h(unsigned s) {
    unsigned t, p;
    asm("mul.rn.f16x2 %0, %1, %2;" : "=r"(t) : "r"(s), "r"(0x2C002C00u));
    asm("tanh.approx.f16x2 %0, %1;" : "=r"(t) : "r"(t));
    asm("fma.rn.f16x2 %0, %1, %2, %3;" : "=r"(p)
        : "r"(t), "r"(0x38003800u), "r"(0x38003800u));
    return p;
}
#define ONES_H2 0x3C003C00u

// ---------------- fp32 -> f16, MLP=4 per thread (16 floats) ----------------
__global__ void cvt_all(const float* __restrict__ x,
                        const float* __restrict__ wq, const float* __restrict__ wk,
                        const float* __restrict__ wv, const float* __restrict__ wo)
{
    int b = blockIdx.x;
    const float* src;
    __half* dst;
    if (b < 1024) {
        src = x + (size_t)b * 4096;
        dst = g_Xh + (size_t)b * 4096;
    } else {
        int w = (b - 1024) >> 8, r = (b - 1024) & 255;
        src = ((w == 0) ? wq : (w == 1) ? wk : (w == 2) ? wv : wo) + (size_t)r * 4096;
        dst = g_Wh[w] + (size_t)r * 4096;
    }
    const int t4 = threadIdx.x * 4;
    float4 v0 = *(const float4*)(src + t4);
    float4 v1 = *(const float4*)(src + 1024 + t4);
    float4 v2 = *(const float4*)(src + 2048 + t4);
    float4 v3 = *(const float4*)(src + 3072 + t4);
    *(__half2*)(dst + t4)            = __floats2half2_rn(v0.x, v0.y);
    *(__half2*)(dst + t4 + 2)        = __floats2half2_rn(v0.z, v0.w);
    *(__half2*)(dst + 1024 + t4)     = __floats2half2_rn(v1.x, v1.y);
    *(__half2*)(dst + 1024 + t4 + 2) = __floats2half2_rn(v1.z, v1.w);
    *(__half2*)(dst + 2048 + t4)     = __floats2half2_rn(v2.x, v2.y);
    *(__half2*)(dst + 2048 + t4 + 2) = __floats2half2_rn(v2.z, v2.w);
    *(__half2*)(dst + 3072 + t4)     = __floats2half2_rn(v3.x, v3.y);
    *(__half2*)(dst + 3072 + t4 + 2) = __floats2half2_rn(v3.z, v3.w);
}

// ---------------- projection GEMM: 4 warps, warp 64x64, f16 C, occ 3 ----------------
// C[M=4096,N=1024] = A[M,1024] . W[N,1024]^T (+bias)
// grid.z + base_mode -> mode. 0/1/2: per-head Q/K/V f16; 3: out = x + alpha*(C+bias)
__global__ __launch_bounds__(128, 3) void proj_mma(
    const float* __restrict__ b0p, const float* __restrict__ b1p,
    const float* __restrict__ b2p, int base_mode,
    const float* __restrict__ xres, const float* __restrict__ alphap,
    float* __restrict__ outf)
{
    extern __shared__ char smraw[];
    const int tid  = threadIdx.x;
    const int lane = tid & 31, wid = tid >> 5;
    const int wm = wid >> 1, wn = wid & 1;       // 2x2 warps; warp tile 64x64
    const int mode = base_mode + blockIdx.z;
    const float* bias = (blockIdx.z == 0) ? b0p : (blockIdx.z == 1) ? b1p : b2p;
    const int bm = blockIdx.y * 128, bn = blockIdx.x * 128;

    const __half* A = (mode == 3) ? g_Oh : g_Xh;
    const __half* W = g_Wh[mode];
    const __half* Ag = A + (size_t)bm * DM;
    const __half* Wg = W + (size_t)bn * DM;

    unsigned sb = (unsigned)__cvta_generic_to_shared(smraw);

    auto issue = [&](int kt, int s) {
        const unsigned dA = sb + (unsigned)s * PSTG;
        const unsigned dB = dA + 10240;
        const int koff = kt * 32;
        #pragma unroll
        for (int i = 0; i < 4; i++) {
            int e = tid + i * 128;
            int row = e >> 2, c16 = e & 3;
            cpa16(dA + row * 80 + c16 * 16, Ag + (size_t)row * DM + koff + c16 * 8);
            cpa16(dB + row * 80 + c16 * 16, Wg + (size_t)row * DM + koff + c16 * 8);
        }
        CP_COMMIT();
    };

    unsigned c[4][8][2];
    #pragma unroll
    for (int i = 0; i < 4; i++)
        #pragma unroll
        for (int j = 0; j < 8; j++) { c[i][j][0] = 0u; c[i][j][1] = 0u; }

    const int a_row  = lane & 15;
    const int a_coff = (lane >> 4) << 3;
    const int b_row  = (lane & 7) + ((lane >> 4) << 3);
    const int b_coff = lane & 8;

    issue(0, 0);
    issue(1, 1);

    for (int kt = 0; kt < 32; kt++) {
        if (kt < 31) CP_WAIT1(); else CP_WAIT0();
        __syncthreads();
        if (kt + 2 < 32) issue(kt + 2, (kt + 2) % 3);

        const unsigned cA = sb + (unsigned)(kt % 3) * PSTG;
        const unsigned cB = cA + 10240;
        #pragma unroll
        for (int d = 0; d < 32; d += 16) {
            unsigned af[4][4];
            #pragma unroll
            for (int mi = 0; mi < 4; mi++)
                ldsm4(af[mi][0], af[mi][1], af[mi][2], af[mi][3],
                      cA + (unsigned)(((wm * 64 + mi * 16 + a_row) * GS + d + a_coff) * 2));
            #pragma unroll
            for (int np = 0; np < 4; np++) {
                unsigned b0, b1, b2, b3;
                ldsm4(b0, b1, b2, b3,
                      cB + (unsigned)(((wn * 64 + np * 16 + b_row) * GS + d + b_coff) * 2));
                #pragma unroll
                for (int mi = 0; mi < 4; mi++) {
                    mma_h(c[mi][np * 2],     af[mi][0], af[mi][1], af[mi][2], af[mi][3], b0, b1);
                    mma_h(c[mi][np * 2 + 1], af[mi][0], af[mi][1], af[mi][2], af[mi][3], b2, b3);
                }
            }
        }
    }

    // epilogue: c[mi][ni][0] = row (g), cols (n0,n0+1); c[mi][ni][1] = row (g+8)
    const int g  = lane >> 2;
    const int q2 = (lane & 3) * 2;
    if (mode == 3) {
        const float alpha = *alphap;
        #pragma unroll
        for (int mi = 0; mi < 4; mi++)
            #pragma unroll
            for (int half = 0; half < 2; half++) {
                int m = bm + wm * 64 + mi * 16 + g + half * 8;
                #pragma unroll
                for (int ni = 0; ni < 8; ni++) {
                    int n = bn + wn * 64 + ni * 8 + q2;
                    float2 cv = __half22float2(*(__half2*)&c[mi][ni][half]);
                    float2 o;
                    o.x = xres[(size_t)m * DM + n]     + alpha * (cv.x + bias[n]);
                    o.y = xres[(size_t)m * DM + n + 1] + alpha * (cv.y + bias[n + 1]);
                    *(float2*)&outf[(size_t)m * DM + n] = o;
                }
            }
    } else {
        __half* outp = (mode == 0) ? g_Qh : (mode == 1) ? g_Kh : g_Vh;
        #pragma unroll
        for (int mi = 0; mi < 4; mi++)
            #pragma unroll
            for (int half = 0; half < 2; half++) {
                int m = bm + wm * 64 + mi * 16 + g + half * 8;
                int b_ = m >> 11, t_ = m & 2047;
                #pragma unroll
                for (int ni = 0; ni < 8; ni++) {
                    int n = bn + wn * 64 + ni * 8 + q2;
                    int h = n >> 6, hd = n & 63;
                    size_t rb = ((size_t)(b_ * NH + h) * TT + t_);
                    float2 cv = __half22float2(*(__half2*)&c[mi][ni][half]);
                    *(__half2*)&outp[rb * 64 + hd] =
                        __floats2half2_rn(cv.x + bias[n], cv.y + bias[n + 1]);
                }
            }
    }
}

// ---------------- attention: 8 warps x 16 q-rows, f16 S-C = gate input = PV A-frag ----------------
__global__ __launch_bounds__(256, 2) void attn_mma()
{
    extern __shared__ char smraw[];
    const int tid = threadIdx.x, lane = tid & 31, wid = tid >> 5;
    const int bh = blockIdx.x, qt = blockIdx.y;
    const __half* Qg = g_Qh + (size_t)(bh * TT + qt * 128) * 64;
    const __half* Kg = g_Kh + (size_t)bh * TT * 64;
    const __half* Vg = g_Vh + (size_t)bh * TT * 64;

    unsigned sb = (unsigned)__cvta_generic_to_shared(smraw);

    auto issueKV = [&](int t, int s) {
        const __half* Kt = Kg + (size_t)t * 128 * 64;
        const __half* Vt = Vg + (size_t)t * 128 * 64;
        const unsigned dK = sb + (unsigned)s * ASTG;
        const unsigned dV = dK + 18432;
        #pragma unroll
        for (int i = 0; i < 4; i++) {
            int e = tid + i * 256;
            int row = e >> 3, c16 = e & 7;
            cpa16(dK + row * 144 + c16 * 16, Kt + (size_t)row * 64 + c16 * 8);
            cpa16(dV + row * 144 + c16 * 16, Vt + (size_t)row * 64 + c16 * 8);
        }
        CP_COMMIT();
    };

    issueKV(0, 0);
    issueKV(1, 1);
    {
        const unsigned dQ = sb + 2u * ASTG;
        #pragma unroll
        for (int i = 0; i < 4; i++) {
            int e = tid + i * 256;
            int row = e >> 3, c16 = e & 7;
            cpa16(dQ + row * 144 + c16 * 16, Qg + (size_t)row * 64 + c16 * 8);
        }
        CP_COMMIT();
    }

    const int a_row  = lane & 15;
    const int a_coff = (lane >> 4) << 3;
    const int b_row  = (lane & 7) + ((lane >> 4) << 3);
    const int b_coff = lane & 8;
    const int v_row  = (lane & 7) + (lane & 8);
    const int v_coff = (lane >> 4) << 3;
    const int qr = wid * 16;

    CP_WAIT0();
    __syncthreads();

    unsigned qf[4][4];
    #pragma unroll
    for (int d16 = 0; d16 < 4; d16++)
        ldsm4(qf[d16][0], qf[d16][1], qf[d16][2], qf[d16][3],
              sb + 2u * ASTG + (unsigned)(((qr + a_row) * 144) + (d16 * 16 + a_coff) * 2));

    float oc[8][4];
    #pragma unroll
    for (int i = 0; i < 8; i++)
        #pragma unroll
        for (int j = 0; j < 4; j++) oc[i][j] = 0.f;
    float dc[4] = {0.f, 0.f, 0.f, 0.f};

    for (int kt = 0; kt < 16; kt++) {
        if (kt == 15) CP_WAIT0(); else CP_WAIT1();
        __syncthreads();
        if (kt + 2 < 16) issueKV(kt + 2, (kt + 2) % 3);

        const unsigned cK = sb + (unsigned)(kt % 3) * ASTG;
        const unsigned cV = cK + 18432;

        #pragma unroll
        for (int half = 0; half < 2; half++) {
            // S (f16 C): sc[nt][0] = row g pair, sc[nt][1] = row g+8 pair
            unsigned sc[8][2];
            #pragma unroll
            for (int i = 0; i < 8; i++) { sc[i][0] = 0u; sc[i][1] = 0u; }

            #pragma unroll
            for (int np = 0; np < 4; np++) {
                const int npg = half * 4 + np;
                #pragma unroll
                for (int d16 = 0; d16 < 4; d16++) {
                    unsigned b0, b1, b2, b3;
                    ldsm4(b0, b1, b2, b3,
                          cK + (unsigned)(((npg * 16 + b_row) * 144) + (d16 * 16 + b_coff) * 2));
                    mma_h(sc[np * 2],     qf[d16][0], qf[d16][1], qf[d16][2], qf[d16][3], b0, b1);
                    mma_h(sc[np * 2 + 1], qf[d16][0], qf[d16][1], qf[d16][2], qf[d16][3], b2, b3);
                }
            }

            // gate in-place (f16x2) -> PV A fragments; denom + PV on tensor pipe
            #pragma unroll
            for (int t = 0; t < 4; t++) {
                const int tg = half * 4 + t;
                unsigned a0 = gate2h(sc[2 * t][0]);
                unsigned a1 = gate2h(sc[2 * t][1]);
                unsigned a2 = gate2h(sc[2 * t + 1][0]);
                unsigned a3 = gate2h(sc[2 * t + 1][1]);
                mma_hf(dc, a0, a1, a2, a3, ONES_H2, ONES_H2);
                #pragma unroll
                for (int nq = 0; nq < 4; nq++) {
                    unsigned b0, b1, b2, b3;
                    ldsm4t(b0, b1, b2, b3,
                           cV + (unsigned)(((tg * 16 + v_row) * 144) + (nq * 16 + v_coff) * 2));
                    mma_hf(oc[nq * 2],     a0, a1, a2, a3, b0, b1);
                    mma_hf(oc[nq * 2 + 1], a0, a1, a2, a3, b2, b3);
                }
            }
        }
    }

    const float inv0 = 1.f / (dc[0] + 1e-6f);
    const float inv1 = 1.f / (dc[2] + 1e-6f);

    // epilogue: normalized O -> g_Oh [B,T,D] f16
    const int b_ = bh >> 4, h = bh & 15;
    const int g = lane >> 2, q2 = (lane & 3) * 2;
    const int t0 = qt * 128 + qr + g;
    const size_t r0 = (size_t)(b_ * TT + t0) * DM + h * 64;
    const size_t r1 = r0 + (size_t)8 * DM;
    #pragma unroll
    for (int nt = 0; nt < 8; nt++) {
        int hd = nt * 8 + q2;
        *(__half2*)&g_Oh[r0 + hd] = __floats2half2_rn(oc[nt][0] * inv0, oc[nt][1] * inv0);
        *(__half2*)&g_Oh[r1 + hd] = __floats2half2_rn(oc[nt][2] * inv1, oc[nt][3] * inv1);
    }
}

// ---------------------------------------------------------------------------
extern "C" void kernel_launch(void* const* d_in, const int* in_sizes, int n_in,
                              void* d_out, int out_size)
{
    const float* x  = (const float*)d_in[0];
    const float* wq = (const float*)d_in[1];
    const float* bq = (const float*)d_in[2];
    const float* wk = (const float*)d_in[3];
    const float* bk = (const float*)d_in[4];
    const float* wv = (const float*)d_in[5];
    const float* bv = (const float*)d_in[6];
    const float* wo = (const float*)d_in[7];
    const float* bo = (const float*)d_in[8];
    const float* al = (const float*)d_in[9];
    float* out = (float*)d_out;

    cudaFuncSetAttribute(proj_mma, cudaFuncAttributeMaxDynamicSharedMemorySize, PSMEM);
    cudaFuncSetAttribute(attn_mma, cudaFuncAttributeMaxDynamicSharedMemorySize, ASMEM);

    cvt_all<<<2048, 256>>>(x, wq, wk, wv, wo);

    // fused Q/K/V projections (grid.z selects mode 0/1/2)
    proj_mma<<<dim3(DM / 128, MT / 128, 3), 128, PSMEM>>>(bq, bk, bv, 0,
                                                          nullptr, nullptr, nullptr);

    attn_mma<<<dim3(BB * NH, TT / 128), 256, ASMEM>>>();

    // output projection + residual
    proj_mma<<<dim3(DM / 128, MT / 128, 1), 128, PSMEM>>>(bo, bo, bo, 3,
                                                          x, al, out);
}